// round 15
// baseline (speedup 1.0000x reference)
#include <cuda_runtime.h>
#include <cuda_bf16.h>

// ============================================================================
// Node-pair packed kernel (R13 winner + wave-balanced NSPLIT=9):
//   blocks [0, nTiles*NSPLIT): tile = bid % nTiles, split = bid / nTiles.
//     Each block: 256 threads, 512 points (2/thread) x ~57 nodes processed as
//     PACKED NODE-PAIRS (packed lane = node). grid = 1153 ~= 2 full waves at
//     4 blocks/SM resident (was 1.73 waves -> 27%-idle tail).
//   Partials to scratch; LAST split-block per tile combines (fixed order).
//   block nTiles*NSPLIT: edge regularizer.
//
// smem per node-pair: 16 float2 slots, .x = node n0, .y = node n1:
//   0:r00 1:r01 2:r02 3:u0  4:r10 5:r11 6:r12 7:u1
//   8:r20 9:r21 10:r22 11:u2 12:kx 13:ky 14:kz 15:kc
// u = t + c - R*c  (contribution = w * (R*p + u))
// k = 2*SS2*c, kc = -SS2*|c|^2,  SS2 = log2(e)/(2*sigma^2)
// w' = ex2(k.p + kc) = w * 2^{q2}; per-point scale cancels; epilogue uses
// eps = 1e-5 * 2^{q2}.
// ============================================================================

#define BLOCK_THREADS 256
#define PTS_PER_BLOCK 512      // 2 points per thread
#define NSPLIT 9
#define MAXP 65536
#define MAXTILES (MAXP / PTS_PER_BLOCK + 1)

__device__ float4 g_part[NSPLIT * MAXP];        // (ax, ay, az, S) partials
__device__ unsigned int g_tilecount[MAXTILES];  // monotone counters (mod NSPLIT)

typedef unsigned long long ull;

// ---- packed f32x2 helpers (sm_103a) ----------------------------------------
__device__ __forceinline__ ull pk2(float a, float b) {
    ull r;
    asm("mov.b64 %0, {%1, %2};" : "=l"(r) : "f"(a), "f"(b));
    return r;
}
__device__ __forceinline__ void upk2(ull v, float& a, float& b) {
    asm("mov.b64 {%0, %1}, %2;" : "=f"(a), "=f"(b) : "l"(v));
}
__device__ __forceinline__ ull add2(ull a, ull b) {
    ull r;
    asm("add.rn.f32x2 %0, %1, %2;" : "=l"(r) : "l"(a), "l"(b));
    return r;
}
__device__ __forceinline__ ull fma2(ull a, ull b, ull c) {
    ull r;
    asm("fma.rn.f32x2 %0, %1, %2, %3;" : "=l"(r) : "l"(a), "l"(b), "l"(c));
    return r;
}
__device__ __forceinline__ float ex2f(float x) {
    float r;
    asm("ex2.approx.f32 %0, %1;" : "=f"(r) : "f"(x));
    return r;
}

// ---- Rodrigues --------------------------------------------------------------
__device__ __forceinline__ void rodrigues(float x, float y, float z, float R[9]) {
    float th2 = x * x + y * y + z * z + 1e-12f;
    float th = sqrtf(th2);
    float s, co;
    sincosf(th, &s, &co);
    float a = s / th;
    float b = (1.0f - co) / th2;
    float xx = x * x, yy = y * y, zz = z * z;
    float xy = x * y, xz = x * z, yz = y * z;
    R[0] = 1.0f - b * (yy + zz);
    R[1] = -a * z + b * xy;
    R[2] =  a * y + b * xz;
    R[3] =  a * z + b * xy;
    R[4] = 1.0f - b * (xx + zz);
    R[5] = -a * x + b * yz;
    R[6] = -a * y + b * xz;
    R[7] =  a * x + b * yz;
    R[8] = 1.0f - b * (xx + yy);
}

#define SS2 0.0288539008f   // 0.02 * log2(e)

// node constant bundle
struct NodeC {
    float r[9];
    float u[3];
    float k[3];
    float kc;
};

__device__ __forceinline__ void node_constants(const float* cp, const float* rv,
                                               const float* t, int n, NodeC& o) {
    rodrigues(rv[3 * n + 0], rv[3 * n + 1], rv[3 * n + 2], o.r);
    float cx = cp[3 * n + 0], cy = cp[3 * n + 1], cz = cp[3 * n + 2];
    float tx = t[3 * n + 0],  ty = t[3 * n + 1],  tz = t[3 * n + 2];
    o.u[0] = tx + cx - (o.r[0] * cx + o.r[1] * cy + o.r[2] * cz);
    o.u[1] = ty + cy - (o.r[3] * cx + o.r[4] * cy + o.r[5] * cz);
    o.u[2] = tz + cz - (o.r[6] * cx + o.r[7] * cy + o.r[8] * cz);
    o.k[0] = 2.0f * SS2 * cx;
    o.k[1] = 2.0f * SS2 * cy;
    o.k[2] = 2.0f * SS2 * cz;
    o.kc = -SS2 * (cx * cx + cy * cy + cz * cz);
}

__global__ void __launch_bounds__(BLOCK_THREADS)
main_kernel(const float* __restrict__ pts,
            const float* __restrict__ cp,
            const float* __restrict__ rv,
            const float* __restrict__ t,
            const int* __restrict__ edges,
            float* __restrict__ out,
            int N, int P, int E, int nTiles, int chunk) {
    extern __shared__ float2 sf[];  // 16 float2 per node-pair

    // ------------------------------------------------------------------
    // Edge block (last block)
    // ------------------------------------------------------------------
    if (blockIdx.x == (unsigned)(nTiles * NSPLIT)) {
        __shared__ float red[BLOCK_THREADS];
        float acc = 0.0f;
        for (int m = threadIdx.x; m < E; m += BLOCK_THREADS) {
            int i = edges[2 * m + 0];
            int j = edges[2 * m + 1];
            i = min(max(i, 0), N - 1);
            j = min(max(j, 0), N - 1);

            float R[9];
            rodrigues(rv[3 * i + 0], rv[3 * i + 1], rv[3 * i + 2], R);

            float cix = cp[3 * i + 0], ciy = cp[3 * i + 1], ciz = cp[3 * i + 2];
            float cjx = cp[3 * j + 0], cjy = cp[3 * j + 1], cjz = cp[3 * j + 2];
            float tix = t[3 * i + 0],  tiy = t[3 * i + 1],  tiz = t[3 * i + 2];
            float tjx = t[3 * j + 0],  tjy = t[3 * j + 1],  tjz = t[3 * j + 2];

            float dx = cjx - cix, dy = cjy - ciy, dz = cjz - ciz;

            float r0 = fmaf(R[0], dx, fmaf(R[1], dy, R[2] * dz)) + cix + tix - cjx - tjx;
            float r1 = fmaf(R[3], dx, fmaf(R[4], dy, R[5] * dz)) + ciy + tiy - cjy - tjy;
            float r2 = fmaf(R[6], dx, fmaf(R[7], dy, R[8] * dz)) + ciz + tiz - cjz - tjz;

            acc += r0 * r0 + r1 * r1 + r2 * r2;
        }
        red[threadIdx.x] = acc;
        __syncthreads();
        for (int s = BLOCK_THREADS / 2; s > 0; s >>= 1) {
            if (threadIdx.x < (unsigned)s) red[threadIdx.x] += red[threadIdx.x + s];
            __syncthreads();
        }
        if (threadIdx.x == 0) out[3 * P] = red[0];
        return;
    }

    int split = blockIdx.x / nTiles;
    int tile  = blockIdx.x % nTiles;
    int n0 = split * chunk;
    int nNodes = min(chunk, N - n0);
    if (nNodes < 0) nNodes = 0;
    int nPairs = (nNodes + 1) / 2;

    // ------------------------------------------------------------------
    // Stage node-PAIR constants (packed across nodes, no replication)
    // ------------------------------------------------------------------
    for (int pr = threadIdx.x; pr < nPairs; pr += BLOCK_THREADS) {
        int nA = n0 + 2 * pr;
        int nB = nA + 1;

        NodeC A, B;
        node_constants(cp, rv, t, nA, A);
        if (nB < n0 + nNodes) {
            node_constants(cp, rv, t, nB, B);
        } else {
            for (int q = 0; q < 9; ++q) B.r[q] = 0.0f;
            B.u[0] = B.u[1] = B.u[2] = 0.0f;
            B.k[0] = B.k[1] = B.k[2] = 0.0f;
            B.kc = -1e30f;   // ex2 -> 0: zero contribution
        }

        float2* s = sf + 16 * pr;
        s[0]  = make_float2(A.r[0], B.r[0]);
        s[1]  = make_float2(A.r[1], B.r[1]);
        s[2]  = make_float2(A.r[2], B.r[2]);
        s[3]  = make_float2(A.u[0], B.u[0]);
        s[4]  = make_float2(A.r[3], B.r[3]);
        s[5]  = make_float2(A.r[4], B.r[4]);
        s[6]  = make_float2(A.r[5], B.r[5]);
        s[7]  = make_float2(A.u[1], B.u[1]);
        s[8]  = make_float2(A.r[6], B.r[6]);
        s[9]  = make_float2(A.r[7], B.r[7]);
        s[10] = make_float2(A.r[8], B.r[8]);
        s[11] = make_float2(A.u[2], B.u[2]);
        s[12] = make_float2(A.k[0], B.k[0]);
        s[13] = make_float2(A.k[1], B.k[1]);
        s[14] = make_float2(A.k[2], B.k[2]);
        s[15] = make_float2(A.kc,   B.kc);
    }
    __syncthreads();

    // ------------------------------------------------------------------
    // 2 points per thread; each iter handles 2 packed nodes for both.
    // ------------------------------------------------------------------
    int base = tile * PTS_PER_BLOCK;
    int p0 = base + threadIdx.x;
    int p1 = p0 + BLOCK_THREADS;
    int l0 = p0 < P ? p0 : 0;
    int l1 = p1 < P ? p1 : 0;

    ull PX0, PY0, PZ0, PX1, PY1, PZ1;
    {
        float x = pts[3 * l0 + 0], y = pts[3 * l0 + 1], z = pts[3 * l0 + 2];
        PX0 = pk2(x, x); PY0 = pk2(y, y); PZ0 = pk2(z, z);
        x = pts[3 * l1 + 0]; y = pts[3 * l1 + 1]; z = pts[3 * l1 + 2];
        PX1 = pk2(x, x); PY1 = pk2(y, y); PZ1 = pk2(z, z);
    }

    ull ax0 = 0ull, ay0 = 0ull, az0 = 0ull, S0 = 0ull;
    ull ax1 = 0ull, ay1 = 0ull, az1 = 0ull, S1 = 0ull;

    const ulonglong2* smp = (const ulonglong2*)sf;

#pragma unroll 4
    for (int pr = 0; pr < nPairs; ++pr) {
        ulonglong2 a0 = smp[0];  // (r00, r01)
        ulonglong2 a1 = smp[1];  // (r02, u0)
        ulonglong2 a2 = smp[2];  // (r10, r11)
        ulonglong2 a3 = smp[3];  // (r12, u1)
        ulonglong2 a4 = smp[4];  // (r20, r21)
        ulonglong2 a5 = smp[5];  // (r22, u2)
        ulonglong2 a6 = smp[6];  // (kx, ky)
        ulonglong2 a7 = smp[7];  // (kz, kc)
        smp += 8;

        {
            ull dot = fma2(a6.x, PX0, fma2(a6.y, PY0, fma2(a7.x, PZ0, a7.y)));
            float d0, d1;
            upk2(dot, d0, d1);
            float w0 = ex2f(d0);
            float w1 = ex2f(d1);
            ull ww = pk2(w0, w1);

            ull y0 = fma2(a0.x, PX0, fma2(a0.y, PY0, fma2(a1.x, PZ0, a1.y)));
            ull y1 = fma2(a2.x, PX0, fma2(a2.y, PY0, fma2(a3.x, PZ0, a3.y)));
            ull y2 = fma2(a4.x, PX0, fma2(a4.y, PY0, fma2(a5.x, PZ0, a5.y)));

            ax0 = fma2(ww, y0, ax0);
            ay0 = fma2(ww, y1, ay0);
            az0 = fma2(ww, y2, az0);
            S0 = add2(S0, ww);
        }
        {
            ull dot = fma2(a6.x, PX1, fma2(a6.y, PY1, fma2(a7.x, PZ1, a7.y)));
            float d0, d1;
            upk2(dot, d0, d1);
            float w0 = ex2f(d0);
            float w1 = ex2f(d1);
            ull ww = pk2(w0, w1);

            ull y0 = fma2(a0.x, PX1, fma2(a0.y, PY1, fma2(a1.x, PZ1, a1.y)));
            ull y1 = fma2(a2.x, PX1, fma2(a2.y, PY1, fma2(a3.x, PZ1, a3.y)));
            ull y2 = fma2(a4.x, PX1, fma2(a4.y, PY1, fma2(a5.x, PZ1, a5.y)));

            ax1 = fma2(ww, y0, ax1);
            ay1 = fma2(ww, y1, ay1);
            az1 = fma2(ww, y2, az1);
            S1 = add2(S1, ww);
        }
    }

    float4* gp = g_part + (size_t)split * P;
    {
        float xa, xb, ya, yb, za, zb, sa, sb;
        upk2(ax0, xa, xb); upk2(ay0, ya, yb); upk2(az0, za, zb); upk2(S0, sa, sb);
        if (p0 < P) gp[p0] = make_float4(xa + xb, ya + yb, za + zb, sa + sb);
        upk2(ax1, xa, xb); upk2(ay1, ya, yb); upk2(az1, za, zb); upk2(S1, sa, sb);
        if (p1 < P) gp[p1] = make_float4(xa + xb, ya + yb, za + zb, sa + sb);
    }

    // ------------------------------------------------------------------
    // Last split-block of this tile combines (fixed split order -> deterministic)
    // out = ax' / (S' + 1e-5 * 2^{q2})
    // ------------------------------------------------------------------
    __threadfence();
    __shared__ unsigned int sOld;
    if (threadIdx.x == 0)
        sOld = atomicAdd(&g_tilecount[tile], 1u);
    __syncthreads();
    if ((sOld % NSPLIT) != (NSPLIT - 1)) return;

#pragma unroll
    for (int q = 0; q < 2; ++q) {
        int p = base + q * BLOCK_THREADS + threadIdx.x;
        if (p >= P) break;
        float axv = 0.0f, ayv = 0.0f, azv = 0.0f, Sv = 0.0f;
#pragma unroll
        for (int s = 0; s < NSPLIT; ++s) {
            float4 v = __ldcg(&g_part[(size_t)s * P + p]);  // L2-coherent read
            axv += v.x; ayv += v.y; azv += v.z; Sv += v.w;
        }
        float ppx = pts[3 * p + 0], ppy = pts[3 * p + 1], ppz = pts[3 * p + 2];
        float q2 = SS2 * (ppx * ppx + ppy * ppy + ppz * ppz);
        float eps = 1e-5f * ex2f(q2);
        float inv = 1.0f / (Sv + eps);
        out[3 * p + 0] = axv * inv;
        out[3 * p + 1] = ayv * inv;
        out[3 * p + 2] = azv * inv;
    }
}

// ---------------------------------------------------------------------------
extern "C" void kernel_launch(void* const* d_in, const int* in_sizes, int n_in,
                              void* d_out, int out_size) {
    const float* points  = (const float*)d_in[0];
    const float* cp      = (const float*)d_in[1];
    const float* rot_vec = (const float*)d_in[2];
    const float* t       = (const float*)d_in[3];
    const int*   edges   = (const int*)d_in[4];

    float* out = (float*)d_out;

    int P = in_sizes[0] / 3;
    if (P > MAXP) P = MAXP;  // defensive (scratch bound)
    int N = in_sizes[1] / 3;
    int E = in_sizes[4] / 2;

    int nTiles = (P + PTS_PER_BLOCK - 1) / PTS_PER_BLOCK;
    int chunk = (N + NSPLIT - 1) / NSPLIT;
    int nPairs = (chunk + 1) / 2;
    size_t smem = (size_t)nPairs * 16 * sizeof(float2);  // 128 B per node-pair

    main_kernel<<<nTiles * NSPLIT + 1, BLOCK_THREADS, smem>>>(
        points, cp, rot_vec, t, edges, out, N, P, E, nTiles, chunk);
}

// round 16
// speedup vs baseline: 1.0504x; 1.0504x over previous
#include <cuda_runtime.h>
#include <cuda_bf16.h>

// ============================================================================
// Node-pair packed kernel (R13 inner loop + NSPLIT=9 wave balance):
//   blocks [0, nTiles*NSPLIT): tile = bid % nTiles, split = bid / nTiles.
//     Each block: 256 threads, 512 points (2/thread) x ~57 nodes processed as
//     PACKED NODE-PAIRS (packed lane = node). grid = 1153 ~= 1.95 waves at
//     4 blocks/SM resident (1025 was 1.73 waves -> 27%-idle tail wave).
//   Indexed smem addressing (sm[8*pr+i]) — pointer-walk variant costs +20 regs.
//   __launch_bounds__(256,4): reg cap 64 (R13 needed 61; guard vs drift).
//   Partials to scratch; LAST split-block per tile combines (fixed order).
//   block nTiles*NSPLIT: edge regularizer.
//
// smem per node-pair: 16 float2 slots, .x = node n0, .y = node n1:
//   0:r00 1:r01 2:r02 3:u0  4:r10 5:r11 6:r12 7:u1
//   8:r20 9:r21 10:r22 11:u2 12:kx 13:ky 14:kz 15:kc
// u = t + c - R*c  (contribution = w * (R*p + u))
// k = 2*SS2*c, kc = -SS2*|c|^2,  SS2 = log2(e)/(2*sigma^2)
// w' = ex2(k.p + kc) = w * 2^{q2}; per-point scale cancels; epilogue uses
// eps = 1e-5 * 2^{q2}.
// ============================================================================

#define BLOCK_THREADS 256
#define PTS_PER_BLOCK 512      // 2 points per thread
#define NSPLIT 9
#define MAXP 65536
#define MAXTILES (MAXP / PTS_PER_BLOCK + 1)

__device__ float4 g_part[NSPLIT * MAXP];        // (ax, ay, az, S) partials
__device__ unsigned int g_tilecount[MAXTILES];  // monotone counters (mod NSPLIT)

typedef unsigned long long ull;

// ---- packed f32x2 helpers (sm_103a) ----------------------------------------
__device__ __forceinline__ ull pk2(float a, float b) {
    ull r;
    asm("mov.b64 %0, {%1, %2};" : "=l"(r) : "f"(a), "f"(b));
    return r;
}
__device__ __forceinline__ void upk2(ull v, float& a, float& b) {
    asm("mov.b64 {%0, %1}, %2;" : "=f"(a), "=f"(b) : "l"(v));
}
__device__ __forceinline__ ull add2(ull a, ull b) {
    ull r;
    asm("add.rn.f32x2 %0, %1, %2;" : "=l"(r) : "l"(a), "l"(b));
    return r;
}
__device__ __forceinline__ ull fma2(ull a, ull b, ull c) {
    ull r;
    asm("fma.rn.f32x2 %0, %1, %2, %3;" : "=l"(r) : "l"(a), "l"(b), "l"(c));
    return r;
}
__device__ __forceinline__ float ex2f(float x) {
    float r;
    asm("ex2.approx.f32 %0, %1;" : "=f"(r) : "f"(x));
    return r;
}

// ---- Rodrigues --------------------------------------------------------------
__device__ __forceinline__ void rodrigues(float x, float y, float z, float R[9]) {
    float th2 = x * x + y * y + z * z + 1e-12f;
    float th = sqrtf(th2);
    float s, co;
    sincosf(th, &s, &co);
    float a = s / th;
    float b = (1.0f - co) / th2;
    float xx = x * x, yy = y * y, zz = z * z;
    float xy = x * y, xz = x * z, yz = y * z;
    R[0] = 1.0f - b * (yy + zz);
    R[1] = -a * z + b * xy;
    R[2] =  a * y + b * xz;
    R[3] =  a * z + b * xy;
    R[4] = 1.0f - b * (xx + zz);
    R[5] = -a * x + b * yz;
    R[6] = -a * y + b * xz;
    R[7] =  a * x + b * yz;
    R[8] = 1.0f - b * (xx + yy);
}

#define SS2 0.0288539008f   // 0.02 * log2(e)

// node constant bundle
struct NodeC {
    float r[9];
    float u[3];
    float k[3];
    float kc;
};

__device__ __forceinline__ void node_constants(const float* cp, const float* rv,
                                               const float* t, int n, NodeC& o) {
    rodrigues(rv[3 * n + 0], rv[3 * n + 1], rv[3 * n + 2], o.r);
    float cx = cp[3 * n + 0], cy = cp[3 * n + 1], cz = cp[3 * n + 2];
    float tx = t[3 * n + 0],  ty = t[3 * n + 1],  tz = t[3 * n + 2];
    o.u[0] = tx + cx - (o.r[0] * cx + o.r[1] * cy + o.r[2] * cz);
    o.u[1] = ty + cy - (o.r[3] * cx + o.r[4] * cy + o.r[5] * cz);
    o.u[2] = tz + cz - (o.r[6] * cx + o.r[7] * cy + o.r[8] * cz);
    o.k[0] = 2.0f * SS2 * cx;
    o.k[1] = 2.0f * SS2 * cy;
    o.k[2] = 2.0f * SS2 * cz;
    o.kc = -SS2 * (cx * cx + cy * cy + cz * cz);
}

__global__ void __launch_bounds__(BLOCK_THREADS, 4)
main_kernel(const float* __restrict__ pts,
            const float* __restrict__ cp,
            const float* __restrict__ rv,
            const float* __restrict__ t,
            const int* __restrict__ edges,
            float* __restrict__ out,
            int N, int P, int E, int nTiles, int chunk) {
    extern __shared__ float2 sf[];  // 16 float2 per node-pair

    // ------------------------------------------------------------------
    // Edge block (last block)
    // ------------------------------------------------------------------
    if (blockIdx.x == (unsigned)(nTiles * NSPLIT)) {
        __shared__ float red[BLOCK_THREADS];
        float acc = 0.0f;
        for (int m = threadIdx.x; m < E; m += BLOCK_THREADS) {
            int i = edges[2 * m + 0];
            int j = edges[2 * m + 1];
            i = min(max(i, 0), N - 1);
            j = min(max(j, 0), N - 1);

            float R[9];
            rodrigues(rv[3 * i + 0], rv[3 * i + 1], rv[3 * i + 2], R);

            float cix = cp[3 * i + 0], ciy = cp[3 * i + 1], ciz = cp[3 * i + 2];
            float cjx = cp[3 * j + 0], cjy = cp[3 * j + 1], cjz = cp[3 * j + 2];
            float tix = t[3 * i + 0],  tiy = t[3 * i + 1],  tiz = t[3 * i + 2];
            float tjx = t[3 * j + 0],  tjy = t[3 * j + 1],  tjz = t[3 * j + 2];

            float dx = cjx - cix, dy = cjy - ciy, dz = cjz - ciz;

            float r0 = fmaf(R[0], dx, fmaf(R[1], dy, R[2] * dz)) + cix + tix - cjx - tjx;
            float r1 = fmaf(R[3], dx, fmaf(R[4], dy, R[5] * dz)) + ciy + tiy - cjy - tjy;
            float r2 = fmaf(R[6], dx, fmaf(R[7], dy, R[8] * dz)) + ciz + tiz - cjz - tjz;

            acc += r0 * r0 + r1 * r1 + r2 * r2;
        }
        red[threadIdx.x] = acc;
        __syncthreads();
        for (int s = BLOCK_THREADS / 2; s > 0; s >>= 1) {
            if (threadIdx.x < (unsigned)s) red[threadIdx.x] += red[threadIdx.x + s];
            __syncthreads();
        }
        if (threadIdx.x == 0) out[3 * P] = red[0];
        return;
    }

    int split = blockIdx.x / nTiles;
    int tile  = blockIdx.x % nTiles;
    int n0 = split * chunk;
    int nNodes = min(chunk, N - n0);
    if (nNodes < 0) nNodes = 0;
    int nPairs = (nNodes + 1) / 2;

    // ------------------------------------------------------------------
    // Stage node-PAIR constants (packed across nodes, no replication)
    // ------------------------------------------------------------------
    for (int pr = threadIdx.x; pr < nPairs; pr += BLOCK_THREADS) {
        int nA = n0 + 2 * pr;
        int nB = nA + 1;

        NodeC A, B;
        node_constants(cp, rv, t, nA, A);
        if (nB < n0 + nNodes) {
            node_constants(cp, rv, t, nB, B);
        } else {
            for (int q = 0; q < 9; ++q) B.r[q] = 0.0f;
            B.u[0] = B.u[1] = B.u[2] = 0.0f;
            B.k[0] = B.k[1] = B.k[2] = 0.0f;
            B.kc = -1e30f;   // ex2 -> 0: zero contribution
        }

        float2* s = sf + 16 * pr;
        s[0]  = make_float2(A.r[0], B.r[0]);
        s[1]  = make_float2(A.r[1], B.r[1]);
        s[2]  = make_float2(A.r[2], B.r[2]);
        s[3]  = make_float2(A.u[0], B.u[0]);
        s[4]  = make_float2(A.r[3], B.r[3]);
        s[5]  = make_float2(A.r[4], B.r[4]);
        s[6]  = make_float2(A.r[5], B.r[5]);
        s[7]  = make_float2(A.u[1], B.u[1]);
        s[8]  = make_float2(A.r[6], B.r[6]);
        s[9]  = make_float2(A.r[7], B.r[7]);
        s[10] = make_float2(A.r[8], B.r[8]);
        s[11] = make_float2(A.u[2], B.u[2]);
        s[12] = make_float2(A.k[0], B.k[0]);
        s[13] = make_float2(A.k[1], B.k[1]);
        s[14] = make_float2(A.k[2], B.k[2]);
        s[15] = make_float2(A.kc,   B.kc);
    }
    __syncthreads();

    // ------------------------------------------------------------------
    // 2 points per thread; each iter handles 2 packed nodes for both.
    // ------------------------------------------------------------------
    int base = tile * PTS_PER_BLOCK;
    int p0 = base + threadIdx.x;
    int p1 = p0 + BLOCK_THREADS;
    int l0 = p0 < P ? p0 : 0;
    int l1 = p1 < P ? p1 : 0;

    ull PX0, PY0, PZ0, PX1, PY1, PZ1;
    {
        float x = pts[3 * l0 + 0], y = pts[3 * l0 + 1], z = pts[3 * l0 + 2];
        PX0 = pk2(x, x); PY0 = pk2(y, y); PZ0 = pk2(z, z);
        x = pts[3 * l1 + 0]; y = pts[3 * l1 + 1]; z = pts[3 * l1 + 2];
        PX1 = pk2(x, x); PY1 = pk2(y, y); PZ1 = pk2(z, z);
    }

    ull ax0 = 0ull, ay0 = 0ull, az0 = 0ull, S0 = 0ull;
    ull ax1 = 0ull, ay1 = 0ull, az1 = 0ull, S1 = 0ull;

    const ulonglong2* sm = (const ulonglong2*)sf;

#pragma unroll 4
    for (int pr = 0; pr < nPairs; ++pr) {
        ulonglong2 a0 = sm[8 * pr + 0];  // (r00, r01)
        ulonglong2 a1 = sm[8 * pr + 1];  // (r02, u0)
        ulonglong2 a2 = sm[8 * pr + 2];  // (r10, r11)
        ulonglong2 a3 = sm[8 * pr + 3];  // (r12, u1)
        ulonglong2 a4 = sm[8 * pr + 4];  // (r20, r21)
        ulonglong2 a5 = sm[8 * pr + 5];  // (r22, u2)
        ulonglong2 a6 = sm[8 * pr + 6];  // (kx, ky)
        ulonglong2 a7 = sm[8 * pr + 7];  // (kz, kc)

        {
            ull dot = fma2(a6.x, PX0, fma2(a6.y, PY0, fma2(a7.x, PZ0, a7.y)));
            float d0, d1;
            upk2(dot, d0, d1);
            float w0 = ex2f(d0);
            float w1 = ex2f(d1);
            ull ww = pk2(w0, w1);

            ull y0 = fma2(a0.x, PX0, fma2(a0.y, PY0, fma2(a1.x, PZ0, a1.y)));
            ull y1 = fma2(a2.x, PX0, fma2(a2.y, PY0, fma2(a3.x, PZ0, a3.y)));
            ull y2 = fma2(a4.x, PX0, fma2(a4.y, PY0, fma2(a5.x, PZ0, a5.y)));

            ax0 = fma2(ww, y0, ax0);
            ay0 = fma2(ww, y1, ay0);
            az0 = fma2(ww, y2, az0);
            S0 = add2(S0, ww);
        }
        {
            ull dot = fma2(a6.x, PX1, fma2(a6.y, PY1, fma2(a7.x, PZ1, a7.y)));
            float d0, d1;
            upk2(dot, d0, d1);
            float w0 = ex2f(d0);
            float w1 = ex2f(d1);
            ull ww = pk2(w0, w1);

            ull y0 = fma2(a0.x, PX1, fma2(a0.y, PY1, fma2(a1.x, PZ1, a1.y)));
            ull y1 = fma2(a2.x, PX1, fma2(a2.y, PY1, fma2(a3.x, PZ1, a3.y)));
            ull y2 = fma2(a4.x, PX1, fma2(a4.y, PY1, fma2(a5.x, PZ1, a5.y)));

            ax1 = fma2(ww, y0, ax1);
            ay1 = fma2(ww, y1, ay1);
            az1 = fma2(ww, y2, az1);
            S1 = add2(S1, ww);
        }
    }

    float4* gp = g_part + (size_t)split * P;
    {
        float xa, xb, ya, yb, za, zb, sa, sb;
        upk2(ax0, xa, xb); upk2(ay0, ya, yb); upk2(az0, za, zb); upk2(S0, sa, sb);
        if (p0 < P) gp[p0] = make_float4(xa + xb, ya + yb, za + zb, sa + sb);
        upk2(ax1, xa, xb); upk2(ay1, ya, yb); upk2(az1, za, zb); upk2(S1, sa, sb);
        if (p1 < P) gp[p1] = make_float4(xa + xb, ya + yb, za + zb, sa + sb);
    }

    // ------------------------------------------------------------------
    // Last split-block of this tile combines (fixed split order -> deterministic)
    // out = ax' / (S' + 1e-5 * 2^{q2})
    // ------------------------------------------------------------------
    __threadfence();
    __shared__ unsigned int sOld;
    if (threadIdx.x == 0)
        sOld = atomicAdd(&g_tilecount[tile], 1u);
    __syncthreads();
    if ((sOld % NSPLIT) != (NSPLIT - 1)) return;

#pragma unroll
    for (int q = 0; q < 2; ++q) {
        int p = base + q * BLOCK_THREADS + threadIdx.x;
        if (p >= P) break;
        float axv = 0.0f, ayv = 0.0f, azv = 0.0f, Sv = 0.0f;
#pragma unroll
        for (int s = 0; s < NSPLIT; ++s) {
            float4 v = __ldcg(&g_part[(size_t)s * P + p]);  // L2-coherent read
            axv += v.x; ayv += v.y; azv += v.z; Sv += v.w;
        }
        float ppx = pts[3 * p + 0], ppy = pts[3 * p + 1], ppz = pts[3 * p + 2];
        float q2 = SS2 * (ppx * ppx + ppy * ppy + ppz * ppz);
        float eps = 1e-5f * ex2f(q2);
        float inv = 1.0f / (Sv + eps);
        out[3 * p + 0] = axv * inv;
        out[3 * p + 1] = ayv * inv;
        out[3 * p + 2] = azv * inv;
    }
}

// ---------------------------------------------------------------------------
extern "C" void kernel_launch(void* const* d_in, const int* in_sizes, int n_in,
                              void* d_out, int out_size) {
    const float* points  = (const float*)d_in[0];
    const float* cp      = (const float*)d_in[1];
    const float* rot_vec = (const float*)d_in[2];
    const float* t       = (const float*)d_in[3];
    const int*   edges   = (const int*)d_in[4];

    float* out = (float*)d_out;

    int P = in_sizes[0] / 3;
    if (P > MAXP) P = MAXP;  // defensive (scratch bound)
    int N = in_sizes[1] / 3;
    int E = in_sizes[4] / 2;

    int nTiles = (P + PTS_PER_BLOCK - 1) / PTS_PER_BLOCK;
    int chunk = (N + NSPLIT - 1) / NSPLIT;
    int nPairs = (chunk + 1) / 2;
    size_t smem = (size_t)nPairs * 16 * sizeof(float2);  // 128 B per node-pair

    main_kernel<<<nTiles * NSPLIT + 1, BLOCK_THREADS, smem>>>(
        points, cp, rot_vec, t, edges, out, N, P, E, nTiles, chunk);
}